// round 6
// baseline (speedup 1.0000x reference)
#include <cuda_runtime.h>

// Problem constants (fixed by the dataset: B=16, H=W=512, K=1024)
#define NB    16
#define HH    512
#define WW    512
#define KK    1024
#define NROWS (NB * KK)        // 16384 segments / tokens
#define NPIX  (HH * WW)        // 262144 pixels per image
#define NQUAD (NB * NPIX / 4)  // 1048576 float4/int4 quads
#define BN_EPS 1e-5f

// Scratch (device globals — no runtime allocation allowed)
__device__ float4 g_acc[NROWS];          // per-segment sums: fx, fy, xx, yy
__device__ float  g_cnt[NROWS];          // per-segment counts
__device__ float  g_y[64 * NROWS];       // layer-1 pre-BN activations, feature-major
__device__ float  g_z[32 * NROWS];       // layer-2 pre-BN activations, feature-major
__device__ float  g_s1[128];             // BN1 stats: sum[64], sumsq[64]
__device__ float  g_s2[64];              // BN2 stats: sum[32], sumsq[32]

// ---------------------------------------------------------------------------
// K0: zero the accumulators (out must be rebuilt every launch)
// ---------------------------------------------------------------------------
__global__ void k_zero() {
    int i = blockIdx.x * blockDim.x + threadIdx.x;   // 64*256 = 16384 threads
    g_acc[i] = make_float4(0.f, 0.f, 0.f, 0.f);
    g_cnt[i] = 0.f;
    if (i < 128) g_s1[i] = 0.f;
    if (i < 64)  g_s2[i] = 0.f;
}

// ---------------------------------------------------------------------------
// K1: pooling via global vector REDs.
// One thread = 4 consecutive pixels (same row i, columns j..j+3).
// Per pixel: 1x RED.128 (fx,fy,xx,yy) + 1x RED.32 (count).
// ---------------------------------------------------------------------------
__global__ void k_pool(const int4* __restrict__ lab,
                       const float4* __restrict__ fx4,
                       const float4* __restrict__ fy4) {
    int q = blockIdx.x * blockDim.x + threadIdx.x;
    if (q >= NQUAD) return;

    int4   l = lab[q];
    float4 a = fx4[q];
    float4 b = fy4[q];

    int pix0 = q << 2;
    int img  = pix0 >> 18;              // / NPIX
    int p    = pix0 & (NPIX - 1);
    int i    = p >> 9;                  // row   (dim 2 -> xx)
    int j    = p & (WW - 1);            // col   (dim 3 -> yy)

    const float st = 2.0f / 511.0f;
    float xx = (float)i * st - 1.0f;    // same for all 4 pixels
    float y0 = (float)j * st - 1.0f;
    int base = img << 10;               // img * KK

    int s0 = base + l.x, s1 = base + l.y, s2 = base + l.z, s3 = base + l.w;
    atomicAdd(&g_acc[s0], make_float4(a.x, b.x, xx, y0));
    atomicAdd(&g_acc[s1], make_float4(a.y, b.y, xx, y0 + st));
    atomicAdd(&g_acc[s2], make_float4(a.z, b.z, xx, y0 + 2.f * st));
    atomicAdd(&g_acc[s3], make_float4(a.w, b.w, xx, y0 + 3.f * st));
    atomicAdd(&g_cnt[s0], 1.0f);
    atomicAdd(&g_cnt[s1], 1.0f);
    atomicAdd(&g_cnt[s2], 1.0f);
    atomicAdd(&g_cnt[s3], 1.0f);
}

// ---------------------------------------------------------------------------
// K2: pooled means -> [t, fx, fy, xx, yy] -> linear 5->64 (conv1d k=1),
// store y feature-major, accumulate BN1 sum/sumsq.
// ---------------------------------------------------------------------------
__global__ void k_conv(const float* __restrict__ conv_w,   // [64,5]
                       const float* __restrict__ conv_b,   // [64]
                       const int*   __restrict__ frame_idx,// [16]
                       const int*   __restrict__ n_frames) {
    __shared__ float w[320], bb[64], ssum[64], ssq[64];
    int tid = threadIdx.x;                  // 256
    for (int i = tid; i < 320; i += 256) w[i] = conv_w[i];   // FIX: full 320 load
    if (tid < 64)  { bb[tid] = conv_b[tid]; ssum[tid] = 0.f; ssq[tid] = 0.f; }
    __syncthreads();

    int r = blockIdx.x * 256 + tid;         // 64 blocks -> 16384 rows
    int bimg = r >> 10;
    float t = (float)frame_idx[bimg] / (float)(n_frames[0] - 1);

    float4 a = g_acc[r];
    float  c = fmaxf(g_cnt[r], 1.0f);
    float  inv = 1.0f / c;
    float x0 = t, x1 = a.x * inv, x2 = a.y * inv, x3 = a.z * inv, x4 = a.w * inv;

    int lane = tid & 31;
    for (int f = 0; f < 64; f++) {
        float y = bb[f] + w[f*5]*x0 + w[f*5+1]*x1 + w[f*5+2]*x2
                        + w[f*5+3]*x3 + w[f*5+4]*x4;
        g_y[f * NROWS + r] = y;
        float s = y, q = y * y;
        #pragma unroll
        for (int o = 16; o > 0; o >>= 1) {
            s += __shfl_xor_sync(0xffffffffu, s, o);
            q += __shfl_xor_sync(0xffffffffu, q, o);
        }
        if (lane == 0) { atomicAdd(&ssum[f], s); atomicAdd(&ssq[f], q); }
    }
    __syncthreads();
    if (tid < 64) {
        atomicAdd(&g_s1[tid],      ssum[tid]);
        atomicAdd(&g_s1[64 + tid], ssq[tid]);
    }
}

// ---------------------------------------------------------------------------
// K3: BN1 (from stats) + ReLU + linear 64->32, store z feature-major,
// accumulate BN2 sum/sumsq.
// ---------------------------------------------------------------------------
__global__ void k_lin(const float* __restrict__ lin_w,    // [32,64]
                      const float* __restrict__ lin_b,    // [32]
                      const float* __restrict__ bn1_g,
                      const float* __restrict__ bn1_b) {
    __shared__ float4 lw4[512];                 // [32][16] float4 view of [32][64]
    __shared__ float sc[64], sh[64], ssum[32], ssq[32];
    int tid = threadIdx.x;                      // 128
    const float4* w4 = (const float4*)lin_w;
    for (int i = tid; i < 512; i += 128) lw4[i] = w4[i];
    if (tid < 64) {
        float mean = g_s1[tid] * (1.0f / NROWS);
        float var  = g_s1[64 + tid] * (1.0f / NROWS) - mean * mean;
        float s = bn1_g[tid] * rsqrtf(var + BN_EPS);
        sc[tid] = s;
        sh[tid] = bn1_b[tid] - mean * s;
    }
    if (tid < 32) { ssum[tid] = 0.f; ssq[tid] = 0.f; }
    __syncthreads();

    int r = blockIdx.x * 128 + tid;             // 128 blocks -> 16384 rows
    float z[32];
    #pragma unroll
    for (int o = 0; o < 32; o++) z[o] = __ldg(&lin_b[o]);

    #pragma unroll 4
    for (int fq = 0; fq < 16; fq++) {
        int f = fq * 4;
        float h0 = fmaxf(g_y[(f+0) * NROWS + r] * sc[f+0] + sh[f+0], 0.f);
        float h1 = fmaxf(g_y[(f+1) * NROWS + r] * sc[f+1] + sh[f+1], 0.f);
        float h2 = fmaxf(g_y[(f+2) * NROWS + r] * sc[f+2] + sh[f+2], 0.f);
        float h3 = fmaxf(g_y[(f+3) * NROWS + r] * sc[f+3] + sh[f+3], 0.f);
        #pragma unroll
        for (int o = 0; o < 32; o++) {
            float4 wv = lw4[o * 16 + fq];       // broadcast read
            z[o] += h0 * wv.x + h1 * wv.y + h2 * wv.z + h3 * wv.w;
        }
    }

    int lane = tid & 31;
    #pragma unroll
    for (int o = 0; o < 32; o++) {
        g_z[o * NROWS + r] = z[o];
        float s = z[o], q = z[o] * z[o];
        #pragma unroll
        for (int off = 16; off > 0; off >>= 1) {
            s += __shfl_xor_sync(0xffffffffu, s, off);
            q += __shfl_xor_sync(0xffffffffu, q, off);
        }
        if (lane == 0) { atomicAdd(&ssum[o], s); atomicAdd(&ssq[o], q); }
    }
    __syncthreads();
    if (tid < 32) {
        atomicAdd(&g_s2[tid],      ssum[tid]);
        atomicAdd(&g_s2[32 + tid], ssq[tid]);
    }
}

// ---------------------------------------------------------------------------
// K4: BN2 + ReLU + row L2-normalize, write output row-major [16384, 32]
// ---------------------------------------------------------------------------
__global__ void k_out(const float* __restrict__ bn2_g,
                      const float* __restrict__ bn2_b,
                      float* __restrict__ out) {
    __shared__ float sc[32], sh[32];
    int tid = threadIdx.x;                      // 128
    if (tid < 32) {
        float mean = g_s2[tid] * (1.0f / NROWS);
        float var  = g_s2[32 + tid] * (1.0f / NROWS) - mean * mean;
        float s = bn2_g[tid] * rsqrtf(var + BN_EPS);
        sc[tid] = s;
        sh[tid] = bn2_b[tid] - mean * s;
    }
    __syncthreads();

    int r = blockIdx.x * 128 + tid;             // 128 blocks -> 16384 rows
    float v[32];
    float ss = 0.f;
    #pragma unroll
    for (int o = 0; o < 32; o++) {
        float t = fmaxf(g_z[o * NROWS + r] * sc[o] + sh[o], 0.f);
        v[o] = t;
        ss += t * t;
    }
    float inv = 1.0f / fmaxf(sqrtf(ss), 1e-8f);
    float4* op = (float4*)(out + (size_t)r * 32);
    #pragma unroll
    for (int q = 0; q < 8; q++)
        op[q] = make_float4(v[4*q] * inv, v[4*q+1] * inv, v[4*q+2] * inv, v[4*q+3] * inv);
}

// ---------------------------------------------------------------------------
extern "C" void kernel_launch(void* const* d_in, const int* in_sizes, int n_in,
                              void* d_out, int out_size) {
    const int*   labels  = (const int*)  d_in[0];
    const float* fx      = (const float*)d_in[1];
    const float* fy      = (const float*)d_in[2];
    const int*   fidx    = (const int*)  d_in[3];
    const int*   nfrm    = (const int*)  d_in[4];
    // d_in[5] = n_labels (compile-time 1024)
    const float* conv_w  = (const float*)d_in[6];
    const float* conv_b  = (const float*)d_in[7];
    const float* bn1_g   = (const float*)d_in[8];
    const float* bn1_b   = (const float*)d_in[9];
    const float* lin_w   = (const float*)d_in[10];
    const float* lin_b   = (const float*)d_in[11];
    const float* bn2_g   = (const float*)d_in[12];
    const float* bn2_b   = (const float*)d_in[13];

    k_zero<<<64, 256>>>();
    k_pool<<<NQUAD / 256, 256>>>((const int4*)labels,
                                 (const float4*)fx, (const float4*)fy);
    k_conv<<<64, 256>>>(conv_w, conv_b, fidx, nfrm);
    k_lin<<<128, 128>>>(lin_w, lin_b, bn1_g, bn1_b);
    k_out<<<128, 128>>>(bn2_g, bn2_b, (float*)d_out);
}